// round 2
// baseline (speedup 1.0000x reference)
#include <cuda_runtime.h>
#include <mma.h>
#include <math.h>

using namespace nvcuda;

#define B_    2
#define S_    2048
#define NH_   16
#define HD_   128
#define NC_   32
#define CH_   64
#define QKVW  6144
#define NHD   2048

// ---------------- scratch (device globals; no allocation allowed) ------------
__device__ float g_qkv[(size_t)B_ * S_ * QKVW];                 // ~100 MB
__device__ float g_kv[(size_t)B_ * NH_ * NC_ * HD_ * HD_];      // ~67 MB
__device__ float g_state[(size_t)B_ * NH_ * NC_ * HD_ * HD_];   // ~67 MB
__device__ float g_o[(size_t)B_ * S_ * NHD];                    // ~33 MB
__device__ float g_gate[(size_t)B_ * S_ * NHD];                 // ~33 MB

__device__ __forceinline__ float slope_for(int h) {
    // -base_slope(h) * (1 - (LAYER_IDX-1)/(N_LAYERS-1) + 1e-5), LAYER_IDX=1
    return -exp2f(-0.5f * (float)(h + 1)) * (1.0f + 1e-5f);
}

// ---------------- generic tf32 GEMM: C[M,N] = A[M,K] @ B[K,N] ---------------
// 128x128 tile, BK=16, 8 warps as 2x4, warp tile 64x32 (4x2 wmma 16x16x8 frags)
__global__ void gemm_tf32(const float* __restrict__ A, const float* __restrict__ Bm,
                          float* __restrict__ C, int M, int N, int K)
{
    __shared__ __align__(32) float As[128 * 16];
    __shared__ __align__(32) float Bs[16 * 132];

    const int tid  = threadIdx.x;
    const int warp = tid >> 5;
    const int wr   = warp >> 2;   // 0..1
    const int wc   = warp & 3;    // 0..3
    const int bm   = blockIdx.y * 128;
    const int bn   = blockIdx.x * 128;

    wmma::fragment<wmma::accumulator, 16, 16, 8, float> acc[4][2];
#pragma unroll
    for (int i = 0; i < 4; i++)
#pragma unroll
        for (int j = 0; j < 2; j++) wmma::fill_fragment(acc[i][j], 0.0f);

    for (int k0 = 0; k0 < K; k0 += 16) {
#pragma unroll
        for (int f = tid; f < 512; f += 256) {          // A tile: 128x16
            int r = f >> 2, c = (f & 3) << 2;
            float4 v = *(const float4*)(A + (size_t)(bm + r) * K + k0 + c);
            *(float4*)(As + r * 16 + c) = v;
        }
#pragma unroll
        for (int f = tid; f < 512; f += 256) {          // B tile: 16x128
            int r = f >> 5, c = (f & 31) << 2;
            float4 v = *(const float4*)(Bm + (size_t)(k0 + r) * N + bn + c);
            *(float4*)(Bs + r * 132 + c) = v;
        }
        __syncthreads();

#pragma unroll
        for (int kk = 0; kk < 16; kk += 8) {
            wmma::fragment<wmma::matrix_a, 16, 16, 8, wmma::precision::tf32, wmma::row_major> af[4];
            wmma::fragment<wmma::matrix_b, 16, 16, 8, wmma::precision::tf32, wmma::row_major> bf[2];
#pragma unroll
            for (int i = 0; i < 4; i++) {
                wmma::load_matrix_sync(af[i], As + (wr * 64 + i * 16) * 16 + kk, 16);
#pragma unroll
                for (int t = 0; t < af[i].num_elements; t++)
                    af[i].x[t] = wmma::__float_to_tf32(af[i].x[t]);
            }
#pragma unroll
            for (int j = 0; j < 2; j++) {
                wmma::load_matrix_sync(bf[j], Bs + kk * 132 + wc * 32 + j * 16, 132);
#pragma unroll
                for (int t = 0; t < bf[j].num_elements; t++)
                    bf[j].x[t] = wmma::__float_to_tf32(bf[j].x[t]);
            }
#pragma unroll
            for (int i = 0; i < 4; i++)
#pragma unroll
                for (int j = 0; j < 2; j++)
                    wmma::mma_sync(acc[i][j], af[i], bf[j], acc[i][j]);
        }
        __syncthreads();
    }

#pragma unroll
    for (int i = 0; i < 4; i++)
#pragma unroll
        for (int j = 0; j < 2; j++)
            wmma::store_matrix_sync(C + (size_t)(bm + wr * 64 + i * 16) * N + bn + wc * 32 + j * 16,
                                    acc[i][j], N, wmma::mem_row_major);
}

// -------- per-head RMSNorm + partial RoPE, in place on q/k parts of g_qkv ----
__global__ void norm_rope_kernel(const float* __restrict__ qw,
                                 const float* __restrict__ kw,
                                 const int* __restrict__ positions)
{
    const int bs  = blockIdx.x >> 4;      // 0..B*S-1
    const int h   = blockIdx.x & 15;
    const int sel = blockIdx.y;           // 0=q, 1=k
    const int d   = threadIdx.x;          // 0..127

    float* row = g_qkv + (size_t)bs * QKVW + sel * NHD + h * HD_;
    const float* w = sel ? kw : qw;

    float x = row[d];
    float ss = x * x;
#pragma unroll
    for (int o = 16; o > 0; o >>= 1) ss += __shfl_xor_sync(0xffffffffu, ss, o);

    __shared__ float red[4];
    __shared__ float sh[128];
    if ((d & 31) == 0) red[d >> 5] = ss;
    __syncthreads();
    float tot = red[0] + red[1] + red[2] + red[3];
    float scale = rsqrtf(tot * (1.0f / 128.0f) + 1e-6f);
    float xn = x * scale * w[d];
    sh[d] = xn;
    __syncthreads();

    float outv = xn;
    if (d < 64) {
        int j = d & 31;
        float inv = 1.0f / powf(10000.0f, (float)j * (1.0f / 32.0f));
        float pos = (float)positions[bs & (S_ - 1)];
        float ang = pos * inv;
        float cs = cosf(ang), sn = sinf(ang);
        if (d < 32) outv = sh[d] * cs - sh[d + 32] * sn;
        else        outv = sh[d] * cs + sh[d - 32] * sn;
    }
    row[d] = outv;
}

// -------- per-chunk: intra-chunk output + KV outer product --------------------
// smem: sK[64][129], sQV[64][129] (q then v), sS[64][65], sdec[64]
__global__ void chunk_stats_kernel()
{
    extern __shared__ float sm[];
    float* sK   = sm;
    float* sQV  = sm + 64 * 129;
    float* sS   = sm + 2 * 64 * 129;
    float* sdec = sS + 64 * 65;

    const int bhc = blockIdx.x;
    const int c = bhc & 31, h = (bhc >> 5) & 15, b = bhc >> 9;
    const int tid = threadIdx.x;
    const float slope = slope_for(h);

    const size_t rowbase = ((size_t)(b * S_) + c * 64) * QKVW + h * HD_;

    // load q and k chunks (64 rows x 128)
    for (int f = tid; f < 2048; f += 256) {
        int i = f >> 5, d4 = (f & 31) << 2;
        const float* gp = g_qkv + rowbase + (size_t)i * QKVW + d4;
        float4 q = *(const float4*)(gp);
        float4 k = *(const float4*)(gp + 2048);
        sQV[i * 129 + d4 + 0] = q.x; sQV[i * 129 + d4 + 1] = q.y;
        sQV[i * 129 + d4 + 2] = q.z; sQV[i * 129 + d4 + 3] = q.w;
        sK[i * 129 + d4 + 0] = k.x;  sK[i * 129 + d4 + 1] = k.y;
        sK[i * 129 + d4 + 2] = k.z;  sK[i * 129 + d4 + 3] = k.w;
    }
    if (tid < 64) sdec[tid] = expf(slope * (float)(63 - tid));
    __syncthreads();

    // scores[i][j] = (i>=j) ? (q_i . k_j) * exp(slope*(i-j)) : 0
#pragma unroll
    for (int m = 0; m < 16; m++) {
        int idx = m * 256 + tid;
        int i = idx >> 6, j = idx & 63;
        float acc = 0.0f;
#pragma unroll 4
        for (int d = 0; d < HD_; d++) acc += sQV[i * 129 + d] * sK[j * 129 + d];
        sS[i * 65 + j] = (i >= j) ? acc * expf(slope * (float)(i - j)) : 0.0f;
    }
    __syncthreads();

    // overwrite sQV with v; scale sK rows by k_dec
    for (int f = tid; f < 2048; f += 256) {
        int i = f >> 5, d4 = (f & 31) << 2;
        float4 v = *(const float4*)(g_qkv + rowbase + (size_t)i * QKVW + 4096 + d4);
        sQV[i * 129 + d4 + 0] = v.x; sQV[i * 129 + d4 + 1] = v.y;
        sQV[i * 129 + d4 + 2] = v.z; sQV[i * 129 + d4 + 3] = v.w;
        float kd = sdec[i];
        sK[i * 129 + d4 + 0] *= kd; sK[i * 129 + d4 + 1] *= kd;
        sK[i * 129 + d4 + 2] *= kd; sK[i * 129 + d4 + 3] *= kd;
    }
    __syncthreads();

    // o_intra = scores @ v  -> g_o
    const size_t obase = ((size_t)(b * S_) + c * 64) * NHD + h * HD_;
#pragma unroll
    for (int m = 0; m < 32; m++) {
        int idx = m * 256 + tid;
        int i = idx >> 7, e = idx & 127;
        float acc = 0.0f;
#pragma unroll 4
        for (int j = 0; j < 64; j++) acc += sS[i * 65 + j] * sQV[j * 129 + e];
        g_o[obase + (size_t)i * NHD + e] = acc;
    }

    // KV[d][e] = sum_j (k[j][d]*kdec[j]) * v[j][e]  -> g_kv
    const size_t kvbase = ((size_t)((b * 16 + h) * 32 + c)) * (HD_ * HD_);
#pragma unroll
    for (int m = 0; m < 64; m++) {
        int idx = m * 256 + tid;
        int d = idx >> 7, e = idx & 127;
        float acc = 0.0f;
#pragma unroll 4
        for (int j = 0; j < 64; j++) acc += sK[j * 129 + d] * sQV[j * 129 + e];
        g_kv[kvbase + (size_t)d * HD_ + e] = acc;
    }
}

// -------- sequential chunk-state prefix scan (per b,h) ------------------------
__global__ void scan_kernel(const float* __restrict__ rec)
{
    const int bh = blockIdx.x;     // 0..31
    const int tid = threadIdx.x;   // 256
    const int h = bh & 15;
    const float lam = expf(slope_for(h) * 64.0f);

    float st[64];
    const float* r0 = rec + (size_t)bh * (HD_ * HD_);
#pragma unroll
    for (int m = 0; m < 64; m++) st[m] = r0[m * 256 + tid];

    for (int c = 0; c < 32; c++) {
        float* so = g_state + ((size_t)bh * 32 + c) * (HD_ * HD_);
        const float* kv = g_kv + ((size_t)bh * 32 + c) * (HD_ * HD_);
#pragma unroll
        for (int m = 0; m < 64; m++) {
            so[m * 256 + tid] = st[m];
            st[m] = st[m] * lam + kv[m * 256 + tid];
        }
    }
}

// -------- o_inter = (q * q_dec) @ state_c, accumulated into g_o ---------------
__global__ void o_inter_kernel()
{
    __shared__ float sQ[64 * 129];
    __shared__ float sSlab[16 * 129];

    const int bhc = blockIdx.x;
    const int c = bhc & 31, h = (bhc >> 5) & 15, b = bhc >> 9;
    const int tid = threadIdx.x;
    const float slope = slope_for(h);

    const size_t rowbase = ((size_t)(b * S_) + c * 64) * QKVW + h * HD_;
    for (int f = tid; f < 2048; f += 256) {
        int i = f >> 5, d4 = (f & 31) << 2;
        float4 q = *(const float4*)(g_qkv + rowbase + (size_t)i * QKVW + d4);
        float qd = expf(slope * (float)(i + 1));
        sQ[i * 129 + d4 + 0] = q.x * qd; sQ[i * 129 + d4 + 1] = q.y * qd;
        sQ[i * 129 + d4 + 2] = q.z * qd; sQ[i * 129 + d4 + 3] = q.w * qd;
    }

    float acc[32];
#pragma unroll
    for (int m = 0; m < 32; m++) acc[m] = 0.0f;

    const float* st = g_state + ((size_t)((b * 16 + h) * 32 + c)) * (HD_ * HD_);
    for (int d0 = 0; d0 < HD_; d0 += 16) {
        __syncthreads();
        for (int f = tid; f < 512; f += 256) {
            int r = f >> 5, e4 = (f & 31) << 2;
            float4 v = *(const float4*)(st + (size_t)(d0 + r) * HD_ + e4);
            sSlab[r * 129 + e4 + 0] = v.x; sSlab[r * 129 + e4 + 1] = v.y;
            sSlab[r * 129 + e4 + 2] = v.z; sSlab[r * 129 + e4 + 3] = v.w;
        }
        __syncthreads();
#pragma unroll
        for (int m = 0; m < 32; m++) {
            int idx = m * 256 + tid;
            int i = idx >> 7, e = idx & 127;
            float a = acc[m];
#pragma unroll
            for (int dd = 0; dd < 16; dd++)
                a += sQ[i * 129 + d0 + dd] * sSlab[dd * 129 + e];
            acc[m] = a;
        }
    }

    const size_t obase = ((size_t)(b * S_) + c * 64) * NHD + h * HD_;
#pragma unroll
    for (int m = 0; m < 32; m++) {
        int idx = m * 256 + tid;
        int i = idx >> 7, e = idx & 127;
        g_o[obase + (size_t)i * NHD + e] += acc[m];
    }
}

// -------- grouped RMSNorm + g_norm_w + sigmoid(gate), in place on g_o ---------
__global__ void gating_kernel(const float* __restrict__ gnw)
{
    const int row = blockIdx.x;               // 0..B*S-1
    const int w = threadIdx.x >> 5;           // group 0..7 (256 elems each)
    const int l = threadIdx.x & 31;

    float* op       = g_o    + (size_t)row * NHD + w * 256 + l * 8;
    const float* gp = g_gate + (size_t)row * NHD + w * 256 + l * 8;
    const float* wp = gnw    + w * 256 + l * 8;

    float4 a0 = *(float4*)(op);
    float4 a1 = *(float4*)(op + 4);
    float ss = a0.x * a0.x + a0.y * a0.y + a0.z * a0.z + a0.w * a0.w
             + a1.x * a1.x + a1.y * a1.y + a1.z * a1.z + a1.w * a1.w;
#pragma unroll
    for (int o = 16; o > 0; o >>= 1) ss += __shfl_xor_sync(0xffffffffu, ss, o);
    float scale = rsqrtf(ss * (1.0f / 256.0f) + 1e-6f);

    float4 g0 = *(const float4*)(gp);
    float4 g1 = *(const float4*)(gp + 4);
    float4 w0 = *(const float4*)(wp);
    float4 w1 = *(const float4*)(wp + 4);

    a0.x = a0.x * scale * w0.x * (1.0f / (1.0f + expf(-g0.x)));
    a0.y = a0.y * scale * w0.y * (1.0f / (1.0f + expf(-g0.y)));
    a0.z = a0.z * scale * w0.z * (1.0f / (1.0f + expf(-g0.z)));
    a0.w = a0.w * scale * w0.w * (1.0f / (1.0f + expf(-g0.w)));
    a1.x = a1.x * scale * w1.x * (1.0f / (1.0f + expf(-g1.x)));
    a1.y = a1.y * scale * w1.y * (1.0f / (1.0f + expf(-g1.y)));
    a1.z = a1.z * scale * w1.z * (1.0f / (1.0f + expf(-g1.z)));
    a1.w = a1.w * scale * w1.w * (1.0f / (1.0f + expf(-g1.w)));

    *(float4*)(op)     = a0;
    *(float4*)(op + 4) = a1;
}

// ------------------------------- launcher -------------------------------------
extern "C" void kernel_launch(void* const* d_in, const int* in_sizes, int n_in,
                              void* d_out, int out_size)
{
    const int*   positions = (const int*)d_in[0];
    const float* hidden    = (const float*)d_in[1];
    const float* rec       = (const float*)d_in[2];
    const float* w_qkv     = (const float*)d_in[3];
    const float* w_g       = (const float*)d_in[4];
    const float* w_dense   = (const float*)d_in[5];
    const float* qnw       = (const float*)d_in[6];
    const float* knw       = (const float*)d_in[7];
    const float* gnw       = (const float*)d_in[8];
    float* out = (float*)d_out;

    float *qkvp, *op, *gatep;
    cudaGetSymbolAddress((void**)&qkvp,  g_qkv);
    cudaGetSymbolAddress((void**)&op,    g_o);
    cudaGetSymbolAddress((void**)&gatep, g_gate);

    const int SMEM3 = (2 * 64 * 129 + 64 * 65 + 64) * (int)sizeof(float);  // 82944 B
    cudaFuncSetAttribute(chunk_stats_kernel,
                         cudaFuncAttributeMaxDynamicSharedMemorySize, SMEM3);

    // 1) QKV projection: [4096,2048] @ [2048,6144]
    gemm_tf32<<<dim3(48, 32), 256>>>(hidden, w_qkv, qkvp, B_ * S_, QKVW, 2048);
    // 2) gate projection (independent): [4096,2048] @ [2048,2048]
    gemm_tf32<<<dim3(16, 32), 256>>>(hidden, w_g, gatep, B_ * S_, NHD, 2048);
    // 3) q/k RMSNorm + partial RoPE, in place
    norm_rope_kernel<<<dim3(B_ * S_ * NH_, 2), 128>>>(qnw, knw, positions);
    // 4) per-chunk intra output + KV outer products (parallel over b,h,c)
    chunk_stats_kernel<<<B_ * NH_ * NC_, 256, SMEM3>>>();
    // 5) sequential prefix scan of chunk states (per b,h)
    scan_kernel<<<B_ * NH_, 256>>>(rec);
    // 6) inter-chunk output, accumulated into g_o (parallel over b,h,c)
    o_inter_kernel<<<B_ * NH_ * NC_, 256>>>();
    // 7) grouped RMSNorm + gate
    gating_kernel<<<B_ * S_, 256>>>(gnw);
    // 8) dense output projection -> d_out
    gemm_tf32<<<dim3(16, 32), 256>>>(op, w_dense, out, B_ * S_, NHD, 2048);
}

// round 4
// speedup vs baseline: 1.3800x; 1.3800x over previous
#include <cuda_runtime.h>
#include <mma.h>
#include <math.h>
#include <stdint.h>

using namespace nvcuda;

#define B_    2
#define S_    2048
#define NH_   16
#define HD_   128
#define NC_   32
#define QKVW  6144
#define NHD   2048

__device__ float g_qkv[(size_t)B_ * S_ * QKVW];
__device__ float g_kv[(size_t)B_ * NH_ * NC_ * HD_ * HD_];
__device__ float g_state[(size_t)B_ * NH_ * NC_ * HD_ * HD_];   // reused: rounded hidden, then scan states
__device__ float g_o[(size_t)B_ * S_ * NHD];
__device__ float g_gate[(size_t)B_ * S_ * NHD];
__device__ float g_w[20971520];   // tf32-rounded weights: qkv | g | dense (orig layout)

__device__ __forceinline__ float slope_for(int h) {
    return -exp2f(-0.5f * (float)(h + 1)) * (1.0f + 1e-5f);
}
__device__ __forceinline__ float rna_tf32(float x) {
    unsigned u; asm("cvt.rna.tf32.f32 %0, %1;" : "=r"(u) : "f"(x));
    return __uint_as_float(u);
}
__device__ __forceinline__ uint32_t smem_u32(const void* p) {
    uint32_t a;
    asm("{ .reg .u64 t; cvta.to.shared.u64 t, %1; cvt.u32.u64 %0, t; }" : "=r"(a) : "l"(p));
    return a;
}
__device__ __forceinline__ void cp_async16(uint32_t sa, const void* ga) {
    asm volatile("cp.async.cg.shared.global [%0], [%1], 16;" :: "r"(sa), "l"(ga));
}

// ---------- elementwise tf32 RNA rounding (n multiple of 1024) ----------
__global__ void round_tf32(const float* __restrict__ in, float* __restrict__ out) {
    size_t i = ((size_t)blockIdx.x * 256 + threadIdx.x) * 4;
    float4 v = *(const float4*)(in + i);
    v.x = rna_tf32(v.x); v.y = rna_tf32(v.y); v.z = rna_tf32(v.z); v.w = rna_tf32(v.w);
    *(float4*)(out + i) = v;
}

// ---------- pipelined wmma tf32 GEMM: C[M,N] = A[M,K] @ B[K,N] ----------
// CTA 128x128, BK=32, 2-stage cp.async double buffer, 8 warps (2x4), warp 64x32.
#define AS_LD 36
#define BS_LD 132
__global__ void __launch_bounds__(256, 2)
gemm_pipe(const float* __restrict__ A, const float* __restrict__ Bm,
          float* __restrict__ C, int M, int N, int K)
{
    extern __shared__ float sm[];
    float* As0 = sm;                       // 128*36
    float* As1 = As0 + 128 * AS_LD;
    float* Bs0 = As1 + 128 * AS_LD;        // 32*132
    float* Bs1 = Bs0 + 32 * BS_LD;

    const int tid = threadIdx.x, warp = tid >> 5;
    const int wr = warp >> 2, wc = warp & 3;
    const int bm = blockIdx.y * 128, bn = blockIdx.x * 128;

    const uint32_t uA[2] = { smem_u32(As0), smem_u32(As1) };
    const uint32_t uB[2] = { smem_u32(Bs0), smem_u32(Bs1) };
    float* const pA[2] = { As0, As1 };
    float* const pB[2] = { Bs0, Bs1 };

    wmma::fragment<wmma::accumulator, 16, 16, 8, float> acc[4][2];
#pragma unroll
    for (int i = 0; i < 4; i++)
#pragma unroll
        for (int j = 0; j < 2; j++) wmma::fill_fragment(acc[i][j], 0.0f);

    auto load_stage = [&](int s, int k0) {
#pragma unroll
        for (int j = 0; j < 4; j++) {            // A: 128 rows x 32 cols
            int id = tid + j * 256;
            int r = id >> 3, c = (id & 7) << 2;
            cp_async16(uA[s] + (uint32_t)(r * AS_LD + c) * 4u,
                       A + (size_t)(bm + r) * K + k0 + c);
        }
#pragma unroll
        for (int j = 0; j < 4; j++) {            // B: 32 rows x 128 cols
            int id = tid + j * 256;
            int r = id >> 5, c = (id & 31) << 2;
            cp_async16(uB[s] + (uint32_t)(r * BS_LD + c) * 4u,
                       Bm + (size_t)(k0 + r) * N + bn + c);
        }
        asm volatile("cp.async.commit_group;" ::: "memory");
    };

    const int nk = K >> 5;
    load_stage(0, 0);

    for (int i = 0; i < nk; i++) {
        const int s = i & 1;
        if (i + 1 < nk) {
            load_stage(s ^ 1, (i + 1) << 5);
            asm volatile("cp.async.wait_group 1;" ::: "memory");
        } else {
            asm volatile("cp.async.wait_group 0;" ::: "memory");
        }
        __syncthreads();

        const float* a0 = pA[s] + wr * 64 * AS_LD;
        const float* b0 = pB[s] + wc * 32;
#pragma unroll
        for (int kk = 0; kk < 32; kk += 8) {
            wmma::fragment<wmma::matrix_a, 16, 16, 8, wmma::precision::tf32, wmma::row_major> af[4];
            wmma::fragment<wmma::matrix_b, 16, 16, 8, wmma::precision::tf32, wmma::row_major> bf[2];
#pragma unroll
            for (int x = 0; x < 4; x++)
                wmma::load_matrix_sync(af[x], a0 + x * 16 * AS_LD + kk, AS_LD);
#pragma unroll
            for (int y = 0; y < 2; y++)
                wmma::load_matrix_sync(bf[y], b0 + kk * BS_LD + y * 16, BS_LD);
#pragma unroll
            for (int x = 0; x < 4; x++)
#pragma unroll
                for (int y = 0; y < 2; y++)
                    wmma::mma_sync(acc[x][y], af[x], bf[y], acc[x][y]);
        }
        __syncthreads();
    }

#pragma unroll
    for (int x = 0; x < 4; x++)
#pragma unroll
        for (int y = 0; y < 2; y++)
            wmma::store_matrix_sync(C + (size_t)(bm + wr * 64 + x * 16) * N + bn + wc * 32 + y * 16,
                                    acc[x][y], N, wmma::mem_row_major);
}

// ---------- q/k RMSNorm + partial RoPE, in place ----------
__global__ void norm_rope_kernel(const float* __restrict__ qw,
                                 const float* __restrict__ kw,
                                 const int* __restrict__ positions)
{
    const int bs = blockIdx.x >> 4, h = blockIdx.x & 15, sel = blockIdx.y;
    const int d = threadIdx.x;

    float* row = g_qkv + (size_t)bs * QKVW + sel * NHD + h * HD_;
    const float* w = sel ? kw : qw;

    float x = row[d];
    float ss = x * x;
#pragma unroll
    for (int o = 16; o > 0; o >>= 1) ss += __shfl_xor_sync(0xffffffffu, ss, o);

    __shared__ float red[4];
    __shared__ float sh[128];
    if ((d & 31) == 0) red[d >> 5] = ss;
    __syncthreads();
    float tot = red[0] + red[1] + red[2] + red[3];
    float scale = rsqrtf(tot * (1.0f / 128.0f) + 1e-6f);
    float xn = x * scale * w[d];
    sh[d] = xn;
    __syncthreads();

    float outv = xn;
    if (d < 64) {
        int j = d & 31;
        float inv = 1.0f / powf(10000.0f, (float)j * (1.0f / 32.0f));
        float ang = (float)positions[bs & (S_ - 1)] * inv;
        float cs = cosf(ang), sn = sinf(ang);
        outv = (d < 32) ? sh[d] * cs - sh[d + 32] * sn
                        : sh[d] * cs + sh[d - 32] * sn;
    }
    row[d] = outv;
}

// ---------- per-chunk intra output + KV outer product (register-tiled) ----------
__global__ void __launch_bounds__(256, 2) chunk_stats_kernel()
{
    extern __shared__ float sm[];
    float* sK   = sm;                 // 64*129
    float* sQV  = sm + 64 * 129;      // 64*129
    float* sS   = sm + 2 * 64 * 129;  // 64*65
    float* sdec = sS + 64 * 65;       // 64

    const int bhc = blockIdx.x;
    const int c = bhc & 31, h = (bhc >> 5) & 15, b = bhc >> 9;
    const int tid = threadIdx.x;
    const float slope = slope_for(h);
    const int ty = tid >> 4, tx = tid & 15;

    const size_t rowbase = ((size_t)(b * S_) + c * 64) * QKVW + h * HD_;

    for (int f = tid; f < 2048; f += 256) {
        int i = f >> 5, d4 = (f & 31) << 2;
        const float* gp = g_qkv + rowbase + (size_t)i * QKVW + d4;
        float4 q = *(const float4*)(gp);
        float4 k = *(const float4*)(gp + 2048);
        sQV[i * 129 + d4 + 0] = q.x; sQV[i * 129 + d4 + 1] = q.y;
        sQV[i * 129 + d4 + 2] = q.z; sQV[i * 129 + d4 + 3] = q.w;
        sK[i * 129 + d4 + 0] = k.x;  sK[i * 129 + d4 + 1] = k.y;
        sK[i * 129 + d4 + 2] = k.z;  sK[i * 129 + d4 + 3] = k.w;
    }
    if (tid < 64) sdec[tid] = expf(slope * (float)(63 - tid));
    __syncthreads();

    {   // scores 4x4 per thread
        float a[4][4] = {};
        const int i0 = ty * 4, j0 = tx * 4;
        for (int d = 0; d < 128; d++) {
            float q[4], kk[4];
#pragma unroll
            for (int r = 0; r < 4; r++) q[r] = sQV[(i0 + r) * 129 + d];
#pragma unroll
            for (int cc = 0; cc < 4; cc++) kk[cc] = sK[(j0 + cc) * 129 + d];
#pragma unroll
            for (int r = 0; r < 4; r++)
#pragma unroll
                for (int cc = 0; cc < 4; cc++) a[r][cc] += q[r] * kk[cc];
        }
#pragma unroll
        for (int r = 0; r < 4; r++)
#pragma unroll
            for (int cc = 0; cc < 4; cc++) {
                int i = i0 + r, j = j0 + cc;
                sS[i * 65 + j] = (i >= j) ? a[r][cc] * expf(slope * (float)(i - j)) : 0.0f;
            }
    }
    __syncthreads();

    for (int f = tid; f < 2048; f += 256) {    // sQV <- v, sK *= k_dec
        int i = f >> 5, d4 = (f & 31) << 2;
        float4 v = *(const float4*)(g_qkv + rowbase + (size_t)i * QKVW + 4096 + d4);
        sQV[i * 129 + d4 + 0] = v.x; sQV[i * 129 + d4 + 1] = v.y;
        sQV[i * 129 + d4 + 2] = v.z; sQV[i * 129 + d4 + 3] = v.w;
        float kd = sdec[i];
        sK[i * 129 + d4 + 0] *= kd; sK[i * 129 + d4 + 1] *= kd;
        sK[i * 129 + d4 + 2] *= kd; sK[i * 129 + d4 + 3] *= kd;
    }
    __syncthreads();

    const size_t obase = ((size_t)(b * S_) + c * 64) * NHD + h * HD_;
    {   // o_intra: 4 rows x 8 cols
        float a0[4][4] = {}, a1[4][4] = {};
        const int i0 = ty * 4, e0 = tx * 4;
        for (int j = 0; j < 64; j++) {
            float s[4], v0[4], v1[4];
#pragma unroll
            for (int r = 0; r < 4; r++) s[r] = sS[(i0 + r) * 65 + j];
#pragma unroll
            for (int cc = 0; cc < 4; cc++) {
                v0[cc] = sQV[j * 129 + e0 + cc];
                v1[cc] = sQV[j * 129 + e0 + 64 + cc];
            }
#pragma unroll
            for (int r = 0; r < 4; r++)
#pragma unroll
                for (int cc = 0; cc < 4; cc++) {
                    a0[r][cc] += s[r] * v0[cc];
                    a1[r][cc] += s[r] * v1[cc];
                }
        }
#pragma unroll
        for (int r = 0; r < 4; r++)
#pragma unroll
            for (int cc = 0; cc < 4; cc++) {
                g_o[obase + (size_t)(i0 + r) * NHD + e0 + cc]      = a0[r][cc];
                g_o[obase + (size_t)(i0 + r) * NHD + e0 + 64 + cc] = a1[r][cc];
            }
    }

    {   // KV: 8 rows x 8 cols
        float a0[8][4] = {}, a1[8][4] = {};
        const int d0 = ty * 8, e0 = tx * 4;
        for (int j = 0; j < 64; j++) {
            float kk[8], v0[4], v1[4];
#pragma unroll
            for (int r = 0; r < 8; r++) kk[r] = sK[j * 129 + d0 + r];
#pragma unroll
            for (int cc = 0; cc < 4; cc++) {
                v0[cc] = sQV[j * 129 + e0 + cc];
                v1[cc] = sQV[j * 129 + e0 + 64 + cc];
            }
#pragma unroll
            for (int r = 0; r < 8; r++)
#pragma unroll
                for (int cc = 0; cc < 4; cc++) {
                    a0[r][cc] += kk[r] * v0[cc];
                    a1[r][cc] += kk[r] * v1[cc];
                }
        }
        const size_t kvbase = ((size_t)((b * 16 + h) * 32 + c)) * (HD_ * HD_);
#pragma unroll
        for (int r = 0; r < 8; r++)
#pragma unroll
            for (int cc = 0; cc < 4; cc++) {
                g_kv[kvbase + (size_t)(d0 + r) * HD_ + e0 + cc]      = a0[r][cc];
                g_kv[kvbase + (size_t)(d0 + r) * HD_ + e0 + 64 + cc] = a1[r][cc];
            }
    }
}

// ---------- prefix scan over chunks, parallel across 16384 state elems ----------
__global__ void scan_kernel(const float* __restrict__ rec)
{
    const int bh = blockIdx.x >> 6;
    const int e  = ((blockIdx.x & 63) << 8) + threadIdx.x;
    const float lam = expf(slope_for(bh & 15) * 64.0f);

    float st = rec[(size_t)bh * 16384 + e];
    size_t base = (size_t)bh * 32 * 16384 + e;
#pragma unroll 4
    for (int c = 0; c < 32; c++) {
        g_state[base + (size_t)c * 16384] = st;
        st = st * lam + g_kv[base + (size_t)c * 16384];
    }
}

// ---------- o_inter = (q*q_dec) @ state_c, accumulate into g_o ----------
__global__ void __launch_bounds__(256) o_inter_kernel()
{
    extern __shared__ float sm2[];
    float* sQ  = sm2;              // 64*129
    float* sST = sm2 + 64 * 129;   // 128*129

    const int bhc = blockIdx.x;
    const int c = bhc & 31, h = (bhc >> 5) & 15, b = bhc >> 9;
    const int tid = threadIdx.x;
    const float slope = slope_for(h);
    const int ty = tid >> 4, tx = tid & 15;

    const size_t rowbase = ((size_t)(b * S_) + c * 64) * QKVW + h * HD_;
    for (int f = tid; f < 2048; f += 256) {
        int i = f >> 5, d4 = (f & 31) << 2;
        float4 q = *(const float4*)(g_qkv + rowbase + (size_t)i * QKVW + d4);
        float qd = expf(slope * (float)(i + 1));
        sQ[i * 129 + d4 + 0] = q.x * qd; sQ[i * 129 + d4 + 1] = q.y * qd;
        sQ[i * 129 + d4 + 2] = q.z * qd; sQ[i * 129 + d4 + 3] = q.w * qd;
    }
    const float* st = g_state + ((size_t)((b * 16 + h) * 32 + c)) * (HD_ * HD_);
    for (int f = tid; f < 4096; f += 256) {
        int r = f >> 5, e4 = (f & 31) << 2;
        float4 v = *(const float4*)(st + (size_t)r * HD_ + e4);
        sST[r * 129 + e4 + 0] = v.x; sST[r * 129 + e4 + 1] = v.y;
        sST[r * 129 + e4 + 2] = v.z; sST[r * 129 + e4 + 3] = v.w;
    }
    __syncthreads();

    float a0[4][4] = {}, a1[4][4] = {};
    const int i0 = ty * 4, e0 = tx * 4;
    for (int d = 0; d < 128; d++) {
        float q[4], s0[4], s1[4];
#pragma unroll
        for (int r = 0; r < 4; r++) q[r] = sQ[(i0 + r) * 129 + d];
#pragma unroll
        for (int cc = 0; cc < 4; cc++) {
            s0[cc] = sST[d * 129 + e0 + cc];
            s1[cc] = sST[d * 129 + e0 + 64 + cc];
        }
#pragma unroll
        for (int r = 0; r < 4; r++)
#pragma unroll
            for (int cc = 0; cc < 4; cc++) {
                a0[r][cc] += q[r] * s0[cc];
                a1[r][cc] += q[r] * s1[cc];
            }
    }
    const size_t obase = ((size_t)(b * S_) + c * 64) * NHD + h * HD_;
#pragma unroll
    for (int r = 0; r < 4; r++)
#pragma unroll
        for (int cc = 0; cc < 4; cc++) {
            g_o[obase + (size_t)(i0 + r) * NHD + e0 + cc]      += a0[r][cc];
            g_o[obase + (size_t)(i0 + r) * NHD + e0 + 64 + cc] += a1[r][cc];
        }
}

// ---------- grouped RMSNorm + gate; output rounded to tf32 ----------
__global__ void gating_kernel(const float* __restrict__ gnw)
{
    const int row = blockIdx.x;
    const int w = threadIdx.x >> 5, l = threadIdx.x & 31;

    float* op       = g_o    + (size_t)row * NHD + w * 256 + l * 8;
    const float* gp = g_gate + (size_t)row * NHD + w * 256 + l * 8;
    const float* wp = gnw    + w * 256 + l * 8;

    float4 a0 = *(float4*)(op);
    float4 a1 = *(float4*)(op + 4);
    float ss = a0.x * a0.x + a0.y * a0.y + a0.z * a0.z + a0.w * a0.w
             + a1.x * a1.x + a1.y * a1.y + a1.z * a1.z + a1.w * a1.w;
#pragma unroll
    for (int o = 16; o > 0; o >>= 1) ss += __shfl_xor_sync(0xffffffffu, ss, o);
    float scale = rsqrtf(ss * (1.0f / 256.0f) + 1e-6f);

    float4 g0 = *(const float4*)(gp);
    float4 g1 = *(const float4*)(gp + 4);
    float4 w0 = *(const float4*)(wp);
    float4 w1 = *(const float4*)(wp + 4);

    a0.x = rna_tf32(a0.x * scale * w0.x / (1.0f + expf(-g0.x)));
    a0.y = rna_tf32(a0.y * scale * w0.y / (1.0f + expf(-g0.y)));
    a0.z = rna_tf32(a0.z * scale * w0.z / (1.0f + expf(-g0.z)));
    a0.w = rna_tf32(a0.w * scale * w0.w / (1.0f + expf(-g0.w)));
    a1.x = rna_tf32(a1.x * scale * w1.x / (1.0f + expf(-g1.x)));
    a1.y = rna_tf32(a1.y * scale * w1.y / (1.0f + expf(-g1.y)));
    a1.z = rna_tf32(a1.z * scale * w1.z / (1.0f + expf(-g1.z)));
    a1.w = rna_tf32(a1.w * scale * w1.w / (1.0f + expf(-g1.w)));

    *(float4*)(op)     = a0;
    *(float4*)(op + 4) = a1;
}

// ================================ launcher ===================================
extern "C" void kernel_launch(void* const* d_in, const int* in_sizes, int n_in,
                              void* d_out, int out_size)
{
    const int*   positions = (const int*)d_in[0];
    const float* hidden    = (const float*)d_in[1];
    const float* rec       = (const float*)d_in[2];
    const float* w_qkv     = (const float*)d_in[3];
    const float* w_g       = (const float*)d_in[4];
    const float* w_dense   = (const float*)d_in[5];
    const float* qnw       = (const float*)d_in[6];
    const float* knw       = (const float*)d_in[7];
    const float* gnw       = (const float*)d_in[8];
    float* out = (float*)d_out;

    float *qkvp, *op, *gatep, *wp, *stp;
    cudaGetSymbolAddress((void**)&qkvp,  g_qkv);
    cudaGetSymbolAddress((void**)&op,    g_o);
    cudaGetSymbolAddress((void**)&gatep, g_gate);
    cudaGetSymbolAddress((void**)&wp,    g_w);
    cudaGetSymbolAddress((void**)&stp,   g_state);
    float* wQ = wp;                 // 2048*6144
    float* wG = wp + 12582912;      // 2048*2048
    float* wD = wp + 16777216;      // 2048*2048
    float* hA = stp;                // rounded hidden (g_state reused later by scan)

    const int GSM   = 2 * (128 * AS_LD + 32 * BS_LD) * 4;        // 70656
    const int SMEM3 = (2 * 64 * 129 + 64 * 65 + 64) * 4;          // 82944
    const int SMEM6 = (64 * 129 + 128 * 129) * 4;                 // 99072
    cudaFuncSetAttribute(gemm_pipe, cudaFuncAttributeMaxDynamicSharedMemorySize, GSM);
    cudaFuncSetAttribute(chunk_stats_kernel, cudaFuncAttributeMaxDynamicSharedMemorySize, SMEM3);
    cudaFuncSetAttribute(o_inter_kernel, cudaFuncAttributeMaxDynamicSharedMemorySize, SMEM6);

    // 0) tf32-round all GEMM operands once
    round_tf32<<<12288, 256>>>(w_qkv,   wQ);
    round_tf32<<<4096, 256>>>(w_g,      wG);
    round_tf32<<<4096, 256>>>(w_dense,  wD);
    round_tf32<<<8192, 256>>>(hidden,   hA);

    // 1-2) QKV + gate projections
    gemm_pipe<<<dim3(48, 32), 256, GSM>>>(hA, wQ, qkvp, 4096, QKVW, 2048);
    gemm_pipe<<<dim3(16, 32), 256, GSM>>>(hA, wG, gatep, 4096, NHD, 2048);
    // 3) q/k RMSNorm + partial RoPE
    norm_rope_kernel<<<dim3(B_ * S_ * NH_, 2), 128>>>(qnw, knw, positions);
    // 4) per-chunk intra output + KV outer products
    chunk_stats_kernel<<<B_ * NH_ * NC_, 256, SMEM3>>>();
    // 5) prefix scan (overwrites hA region — GEMMs done)
    scan_kernel<<<2048, 256>>>(rec);
    // 6) inter-chunk output
    o_inter_kernel<<<B_ * NH_ * NC_, 256, SMEM6>>>();
    // 7) grouped RMSNorm + gate (+ tf32 rounding of dense GEMM A operand)
    gating_kernel<<<B_ * S_, 256>>>(gnw);
    // 8) dense projection -> d_out
    gemm_pipe<<<dim3(16, 32), 256, GSM>>>(op, wD, out, 4096, NHD, 2048);
}

// round 5
// speedup vs baseline: 1.4476x; 1.0490x over previous
#include <cuda_runtime.h>
#include <mma.h>
#include <math.h>
#include <stdint.h>

using namespace nvcuda;

#define B_    2
#define S_    2048
#define NH_   16
#define HD_   128
#define NC_   32
#define QKVW  6144
#define NHD   2048

__device__ float g_qkv[(size_t)B_ * S_ * QKVW];
__device__ float g_kv[(size_t)B_ * NH_ * NC_ * HD_ * HD_];
__device__ float g_state[(size_t)B_ * NH_ * NC_ * HD_ * HD_];   // reused: rounded hidden, then scan states
__device__ float g_o[(size_t)B_ * S_ * NHD];
__device__ float g_gate[(size_t)B_ * S_ * NHD];
__device__ float g_w[20971520];   // tf32-rounded weights: qkv | g | dense

__device__ __forceinline__ float slope_for(int h) {
    return -exp2f(-0.5f * (float)(h + 1)) * (1.0f + 1e-5f);
}
__device__ __forceinline__ float rna_tf32(float x) {
    unsigned u; asm("cvt.rna.tf32.f32 %0, %1;" : "=r"(u) : "f"(x));
    return __uint_as_float(u);
}
__device__ __forceinline__ uint32_t smem_u32(const void* p) {
    uint32_t a;
    asm("{ .reg .u64 t; cvta.to.shared.u64 t, %1; cvt.u32.u64 %0, t; }" : "=r"(a) : "l"(p));
    return a;
}
__device__ __forceinline__ void cp_async16(uint32_t sa, const void* ga) {
    asm volatile("cp.async.cg.shared.global [%0], [%1], 16;" :: "r"(sa), "l"(ga));
}

// ---------- elementwise tf32 RNA rounding ----------
__global__ void round_tf32(const float* __restrict__ in, float* __restrict__ out) {
    size_t i = ((size_t)blockIdx.x * 256 + threadIdx.x) * 4;
    float4 v = *(const float4*)(in + i);
    v.x = rna_tf32(v.x); v.y = rna_tf32(v.y); v.z = rna_tf32(v.z); v.w = rna_tf32(v.w);
    *(float4*)(out + i) = v;
}

// ---------- pipelined wmma tf32 GEMM: C[M,N] = A[M,K] @ B[K,N] ----------
// CTA tile 128x256, BK=32, 2-stage cp.async double buffer.
// 8 warps as 2x4, warp tile 64x64 (4x4 wmma 16x16x8 fragments).
#define AS_LD 36
#define BS_LD 264
__global__ void __launch_bounds__(256, 1)
gemm_pipe(const float* __restrict__ A, const float* __restrict__ Bm,
          float* __restrict__ C, int M, int N, int K)
{
    extern __shared__ float sm[];
    float* As0 = sm;                        // 128*36
    float* As1 = As0 + 128 * AS_LD;
    float* Bs0 = As1 + 128 * AS_LD;         // 32*264
    float* Bs1 = Bs0 + 32 * BS_LD;

    const int tid = threadIdx.x, warp = tid >> 5;
    const int wr = warp >> 2, wc = warp & 3;
    const int bm = blockIdx.y * 128, bn = blockIdx.x * 256;

    const uint32_t uA[2] = { smem_u32(As0), smem_u32(As1) };
    const uint32_t uB[2] = { smem_u32(Bs0), smem_u32(Bs1) };
    float* const pA[2] = { As0, As1 };
    float* const pB[2] = { Bs0, Bs1 };

    wmma::fragment<wmma::accumulator, 16, 16, 8, float> acc[4][4];
#pragma unroll
    for (int i = 0; i < 4; i++)
#pragma unroll
        for (int j = 0; j < 4; j++) wmma::fill_fragment(acc[i][j], 0.0f);

    auto load_stage = [&](int s, int k0) {
#pragma unroll
        for (int j = 0; j < 4; j++) {            // A: 128 rows x 32 cols (1024 x 16B)
            int id = tid + j * 256;
            int r = id >> 3, c = (id & 7) << 2;
            cp_async16(uA[s] + (uint32_t)(r * AS_LD + c) * 4u,
                       A + (size_t)(bm + r) * K + k0 + c);
        }
#pragma unroll
        for (int j = 0; j < 8; j++) {            // B: 32 rows x 256 cols (2048 x 16B)
            int id = tid + j * 256;
            int r = id >> 6, c = (id & 63) << 2;
            cp_async16(uB[s] + (uint32_t)(r * BS_LD + c) * 4u,
                       Bm + (size_t)(k0 + r) * N + bn + c);
        }
        asm volatile("cp.async.commit_group;" ::: "memory");
    };

    const int nk = K >> 5;
    load_stage(0, 0);

    for (int i = 0; i < nk; i++) {
        const int s = i & 1;
        if (i + 1 < nk) {
            load_stage(s ^ 1, (i + 1) << 5);
            asm volatile("cp.async.wait_group 1;" ::: "memory");
        } else {
            asm volatile("cp.async.wait_group 0;" ::: "memory");
        }
        __syncthreads();

        const float* a0 = pA[s] + wr * 64 * AS_LD;
        const float* b0 = pB[s] + wc * 64;
#pragma unroll
        for (int kk = 0; kk < 32; kk += 8) {
            wmma::fragment<wmma::matrix_a, 16, 16, 8, wmma::precision::tf32, wmma::row_major> af[4];
            wmma::fragment<wmma::matrix_b, 16, 16, 8, wmma::precision::tf32, wmma::row_major> bf[4];
#pragma unroll
            for (int x = 0; x < 4; x++)
                wmma::load_matrix_sync(af[x], a0 + x * 16 * AS_LD + kk, AS_LD);
#pragma unroll
            for (int y = 0; y < 4; y++)
                wmma::load_matrix_sync(bf[y], b0 + kk * BS_LD + y * 16, BS_LD);
#pragma unroll
            for (int x = 0; x < 4; x++)
#pragma unroll
                for (int y = 0; y < 4; y++)
                    wmma::mma_sync(acc[x][y], af[x], bf[y], acc[x][y]);
        }
        __syncthreads();
    }

#pragma unroll
    for (int x = 0; x < 4; x++)
#pragma unroll
        for (int y = 0; y < 4; y++)
            wmma::store_matrix_sync(C + (size_t)(bm + wr * 64 + x * 16) * N + bn + wc * 64 + y * 16,
                                    acc[x][y], N, wmma::mem_row_major);
}

// ---------- q/k RMSNorm + partial RoPE, in place ----------
__global__ void norm_rope_kernel(const float* __restrict__ qw,
                                 const float* __restrict__ kw,
                                 const int* __restrict__ positions)
{
    const int bs = blockIdx.x >> 4, h = blockIdx.x & 15, sel = blockIdx.y;
    const int d = threadIdx.x;

    float* row = g_qkv + (size_t)bs * QKVW + sel * NHD + h * HD_;
    const float* w = sel ? kw : qw;

    float x = row[d];
    float ss = x * x;
#pragma unroll
    for (int o = 16; o > 0; o >>= 1) ss += __shfl_xor_sync(0xffffffffu, ss, o);

    __shared__ float red[4];
    __shared__ float sh[128];
    if ((d & 31) == 0) red[d >> 5] = ss;
    __syncthreads();
    float tot = red[0] + red[1] + red[2] + red[3];
    float scale = rsqrtf(tot * (1.0f / 128.0f) + 1e-6f);
    float xn = x * scale * w[d];
    sh[d] = xn;
    __syncthreads();

    float outv = xn;
    if (d < 64) {
        int j = d & 31;
        float inv = 1.0f / powf(10000.0f, (float)j * (1.0f / 32.0f));
        float ang = (float)positions[bs & (S_ - 1)] * inv;
        float cs = cosf(ang), sn = sinf(ang);
        outv = (d < 32) ? sh[d] * cs - sh[d + 32] * sn
                        : sh[d] * cs + sh[d - 32] * sn;
    }
    row[d] = outv;
}

// ---------- per-chunk intra output + KV outer product (register-tiled) ----------
__global__ void __launch_bounds__(256, 2) chunk_stats_kernel()
{
    extern __shared__ float sm[];
    float* sK   = sm;                 // 64*129
    float* sQV  = sm + 64 * 129;      // 64*129
    float* sS   = sm + 2 * 64 * 129;  // 64*65
    float* sdec = sS + 64 * 65;       // 64

    const int bhc = blockIdx.x;
    const int c = bhc & 31, h = (bhc >> 5) & 15, b = bhc >> 9;
    const int tid = threadIdx.x;
    const float slope = slope_for(h);
    const int ty = tid >> 4, tx = tid & 15;

    const size_t rowbase = ((size_t)(b * S_) + c * 64) * QKVW + h * HD_;

    for (int f = tid; f < 2048; f += 256) {
        int i = f >> 5, d4 = (f & 31) << 2;
        const float* gp = g_qkv + rowbase + (size_t)i * QKVW + d4;
        float4 q = *(const float4*)(gp);
        float4 k = *(const float4*)(gp + 2048);
        sQV[i * 129 + d4 + 0] = q.x; sQV[i * 129 + d4 + 1] = q.y;
        sQV[i * 129 + d4 + 2] = q.z; sQV[i * 129 + d4 + 3] = q.w;
        sK[i * 129 + d4 + 0] = k.x;  sK[i * 129 + d4 + 1] = k.y;
        sK[i * 129 + d4 + 2] = k.z;  sK[i * 129 + d4 + 3] = k.w;
    }
    if (tid < 64) sdec[tid] = expf(slope * (float)(63 - tid));
    __syncthreads();

    {   // scores 4x4 per thread
        float a[4][4] = {};
        const int i0 = ty * 4, j0 = tx * 4;
        for (int d = 0; d < 128; d++) {
            float q[4], kk[4];
#pragma unroll
            for (int r = 0; r < 4; r++) q[r] = sQV[(i0 + r) * 129 + d];
#pragma unroll
            for (int cc = 0; cc < 4; cc++) kk[cc] = sK[(j0 + cc) * 129 + d];
#pragma unroll
            for (int r = 0; r < 4; r++)
#pragma unroll
                for (int cc = 0; cc < 4; cc++) a[r][cc] += q[r] * kk[cc];
        }
#pragma unroll
        for (int r = 0; r < 4; r++)
#pragma unroll
            for (int cc = 0; cc < 4; cc++) {
                int i = i0 + r, j = j0 + cc;
                sS[i * 65 + j] = (i >= j) ? a[r][cc] * expf(slope * (float)(i - j)) : 0.0f;
            }
    }
    __syncthreads();

    for (int f = tid; f < 2048; f += 256) {    // sQV <- v, sK *= k_dec
        int i = f >> 5, d4 = (f & 31) << 2;
        float4 v = *(const float4*)(g_qkv + rowbase + (size_t)i * QKVW + 4096 + d4);
        sQV[i * 129 + d4 + 0] = v.x; sQV[i * 129 + d4 + 1] = v.y;
        sQV[i * 129 + d4 + 2] = v.z; sQV[i * 129 + d4 + 3] = v.w;
        float kd = sdec[i];
        sK[i * 129 + d4 + 0] *= kd; sK[i * 129 + d4 + 1] *= kd;
        sK[i * 129 + d4 + 2] *= kd; sK[i * 129 + d4 + 3] *= kd;
    }
    __syncthreads();

    const size_t obase = ((size_t)(b * S_) + c * 64) * NHD + h * HD_;
    {   // o_intra: 4 rows x 8 cols
        float a0[4][4] = {}, a1[4][4] = {};
        const int i0 = ty * 4, e0 = tx * 4;
        for (int j = 0; j < 64; j++) {
            float s[4], v0[4], v1[4];
#pragma unroll
            for (int r = 0; r < 4; r++) s[r] = sS[(i0 + r) * 65 + j];
#pragma unroll
            for (int cc = 0; cc < 4; cc++) {
                v0[cc] = sQV[j * 129 + e0 + cc];
                v1[cc] = sQV[j * 129 + e0 + 64 + cc];
            }
#pragma unroll
            for (int r = 0; r < 4; r++)
#pragma unroll
                for (int cc = 0; cc < 4; cc++) {
                    a0[r][cc] += s[r] * v0[cc];
                    a1[r][cc] += s[r] * v1[cc];
                }
        }
#pragma unroll
        for (int r = 0; r < 4; r++)
#pragma unroll
            for (int cc = 0; cc < 4; cc++) {
                g_o[obase + (size_t)(i0 + r) * NHD + e0 + cc]      = a0[r][cc];
                g_o[obase + (size_t)(i0 + r) * NHD + e0 + 64 + cc] = a1[r][cc];
            }
    }

    {   // KV: 8 rows x 8 cols
        float a0[8][4] = {}, a1[8][4] = {};
        const int d0 = ty * 8, e0 = tx * 4;
        for (int j = 0; j < 64; j++) {
            float kk[8], v0[4], v1[4];
#pragma unroll
            for (int r = 0; r < 8; r++) kk[r] = sK[j * 129 + d0 + r];
#pragma unroll
            for (int cc = 0; cc < 4; cc++) {
                v0[cc] = sQV[j * 129 + e0 + cc];
                v1[cc] = sQV[j * 129 + e0 + 64 + cc];
            }
#pragma unroll
            for (int r = 0; r < 8; r++)
#pragma unroll
                for (int cc = 0; cc < 4; cc++) {
                    a0[r][cc] += kk[r] * v0[cc];
                    a1[r][cc] += kk[r] * v1[cc];
                }
        }
        const size_t kvbase = ((size_t)((b * 16 + h) * 32 + c)) * (HD_ * HD_);
#pragma unroll
        for (int r = 0; r < 8; r++)
#pragma unroll
            for (int cc = 0; cc < 4; cc++) {
                g_kv[kvbase + (size_t)(d0 + r) * HD_ + e0 + cc]      = a0[r][cc];
                g_kv[kvbase + (size_t)(d0 + r) * HD_ + e0 + 64 + cc] = a1[r][cc];
            }
    }
}

// ---------- prefix scan over chunks, parallel across 16384 state elems ----------
__global__ void scan_kernel(const float* __restrict__ rec)
{
    const int bh = blockIdx.x >> 6;
    const int e  = ((blockIdx.x & 63) << 8) + threadIdx.x;
    const float lam = expf(slope_for(bh & 15) * 64.0f);

    float st = rec[(size_t)bh * 16384 + e];
    size_t base = (size_t)bh * 32 * 16384 + e;
#pragma unroll 4
    for (int c = 0; c < 32; c++) {
        g_state[base + (size_t)c * 16384] = st;
        st = st * lam + g_kv[base + (size_t)c * 16384];
    }
}

// ---------- o_inter = (q*q_dec) @ state_c, accumulate into g_o ----------
__global__ void __launch_bounds__(256) o_inter_kernel()
{
    extern __shared__ float sm2[];
    float* sQ  = sm2;              // 64*129
    float* sST = sm2 + 64 * 129;   // 128*129

    const int bhc = blockIdx.x;
    const int c = bhc & 31, h = (bhc >> 5) & 15, b = bhc >> 9;
    const int tid = threadIdx.x;
    const float slope = slope_for(h);
    const int ty = tid >> 4, tx = tid & 15;

    const size_t rowbase = ((size_t)(b * S_) + c * 64) * QKVW + h * HD_;
    for (int f = tid; f < 2048; f += 256) {
        int i = f >> 5, d4 = (f & 31) << 2;
        float4 q = *(const float4*)(g_qkv + rowbase + (size_t)i * QKVW + d4);
        float qd = expf(slope * (float)(i + 1));
        sQ[i * 129 + d4 + 0] = q.x * qd; sQ[i * 129 + d4 + 1] = q.y * qd;
        sQ[i * 129 + d4 + 2] = q.z * qd; sQ[i * 129 + d4 + 3] = q.w * qd;
    }
    const float* st = g_state + ((size_t)((b * 16 + h) * 32 + c)) * (HD_ * HD_);
    for (int f = tid; f < 4096; f += 256) {
        int r = f >> 5, e4 = (f & 31) << 2;
        float4 v = *(const float4*)(st + (size_t)r * HD_ + e4);
        sST[r * 129 + e4 + 0] = v.x; sST[r * 129 + e4 + 1] = v.y;
        sST[r * 129 + e4 + 2] = v.z; sST[r * 129 + e4 + 3] = v.w;
    }
    __syncthreads();

    float a0[4][4] = {}, a1[4][4] = {};
    const int i0 = ty * 4, e0 = tx * 4;
    for (int d = 0; d < 128; d++) {
        float q[4], s0[4], s1[4];
#pragma unroll
        for (int r = 0; r < 4; r++) q[r] = sQ[(i0 + r) * 129 + d];
#pragma unroll
        for (int cc = 0; cc < 4; cc++) {
            s0[cc] = sST[d * 129 + e0 + cc];
            s1[cc] = sST[d * 129 + e0 + 64 + cc];
        }
#pragma unroll
        for (int r = 0; r < 4; r++)
#pragma unroll
            for (int cc = 0; cc < 4; cc++) {
                a0[r][cc] += q[r] * s0[cc];
                a1[r][cc] += q[r] * s1[cc];
            }
    }
    const size_t obase = ((size_t)(b * S_) + c * 64) * NHD + h * HD_;
#pragma unroll
    for (int r = 0; r < 4; r++)
#pragma unroll
        for (int cc = 0; cc < 4; cc++) {
            g_o[obase + (size_t)(i0 + r) * NHD + e0 + cc]      += a0[r][cc];
            g_o[obase + (size_t)(i0 + r) * NHD + e0 + 64 + cc] += a1[r][cc];
        }
}

// ---------- grouped RMSNorm + gate; output rounded to tf32 ----------
__global__ void gating_kernel(const float* __restrict__ gnw)
{
    const int row = blockIdx.x;
    const int w = threadIdx.x >> 5, l = threadIdx.x & 31;

    float* op       = g_o    + (size_t)row * NHD + w * 256 + l * 8;
    const float* gp = g_gate + (size_t)row * NHD + w * 256 + l * 8;
    const float* wp = gnw    + w * 256 + l * 8;

    float4 a0 = *(float4*)(op);
    float4 a1 = *(float4*)(op + 4);
    float ss = a0.x * a0.x + a0.y * a0.y + a0.z * a0.z + a0.w * a0.w
             + a1.x * a1.x + a1.y * a1.y + a1.z * a1.z + a1.w * a1.w;
#pragma unroll
    for (int o = 16; o > 0; o >>= 1) ss += __shfl_xor_sync(0xffffffffu, ss, o);
    float scale = rsqrtf(ss * (1.0f / 256.0f) + 1e-6f);

    float4 g0 = *(const float4*)(gp);
    float4 g1 = *(const float4*)(gp + 4);
    float4 w0 = *(const float4*)(wp);
    float4 w1 = *(const float4*)(wp + 4);

    a0.x = rna_tf32(a0.x * scale * w0.x / (1.0f + expf(-g0.x)));
    a0.y = rna_tf32(a0.y * scale * w0.y / (1.0f + expf(-g0.y)));
    a0.z = rna_tf32(a0.z * scale * w0.z / (1.0f + expf(-g0.z)));
    a0.w = rna_tf32(a0.w * scale * w0.w / (1.0f + expf(-g0.w)));
    a1.x = rna_tf32(a1.x * scale * w1.x / (1.0f + expf(-g1.x)));
    a1.y = rna_tf32(a1.y * scale * w1.y / (1.0f + expf(-g1.y)));
    a1.z = rna_tf32(a1.z * scale * w1.z / (1.0f + expf(-g1.z)));
    a1.w = rna_tf32(a1.w * scale * w1.w / (1.0f + expf(-g1.w)));

    *(float4*)(op)     = a0;
    *(float4*)(op + 4) = a1;
}

// ================================ launcher ===================================
extern "C" void kernel_launch(void* const* d_in, const int* in_sizes, int n_in,
                              void* d_out, int out_size)
{
    const int*   positions = (const int*)d_in[0];
    const float* hidden    = (const float*)d_in[1];
    const float* rec       = (const float*)d_in[2];
    const float* w_qkv     = (const float*)d_in[3];
    const float* w_g       = (const float*)d_in[4];
    const float* w_dense   = (const float*)d_in[5];
    const float* qnw       = (const float*)d_in[6];
    const float* knw       = (const float*)d_in[7];
    const float* gnw       = (const float*)d_in[8];
    float* out = (float*)d_out;

    float *qkvp, *op, *gatep, *wp, *stp;
    cudaGetSymbolAddress((void**)&qkvp,  g_qkv);
    cudaGetSymbolAddress((void**)&op,    g_o);
    cudaGetSymbolAddress((void**)&gatep, g_gate);
    cudaGetSymbolAddress((void**)&wp,    g_w);
    cudaGetSymbolAddress((void**)&stp,   g_state);
    float* wQ = wp;                 // 2048*6144
    float* wG = wp + 12582912;      // 2048*2048
    float* wD = wp + 16777216;      // 2048*2048
    float* hA = stp;                // rounded hidden (g_state reused later by scan)

    const int GSM   = 2 * (128 * AS_LD + 32 * BS_LD) * 4;        // 104448
    const int SMEM3 = (2 * 64 * 129 + 64 * 65 + 64) * 4;          // 82944
    const int SMEM6 = (64 * 129 + 128 * 129) * 4;                 // 99072
    cudaFuncSetAttribute(gemm_pipe, cudaFuncAttributeMaxDynamicSharedMemorySize, GSM);
    cudaFuncSetAttribute(chunk_stats_kernel, cudaFuncAttributeMaxDynamicSharedMemorySize, SMEM3);
    cudaFuncSetAttribute(o_inter_kernel, cudaFuncAttributeMaxDynamicSharedMemorySize, SMEM6);

    // 0) tf32-round all GEMM operands once
    round_tf32<<<12288, 256>>>(w_qkv,   wQ);
    round_tf32<<<4096, 256>>>(w_g,      wG);
    round_tf32<<<4096, 256>>>(w_dense,  wD);
    round_tf32<<<8192, 256>>>(hidden,   hA);

    // 1-2) QKV + gate projections (CTA tile 128x256)
    gemm_pipe<<<dim3(24, 32), 256, GSM>>>(hA, wQ, qkvp, 4096, QKVW, 2048);
    gemm_pipe<<<dim3(8, 32), 256, GSM>>>(hA, wG, gatep, 4096, NHD, 2048);
    // 3) q/k RMSNorm + partial RoPE
    norm_rope_kernel<<<dim3(B_ * S_ * NH_, 2), 128>>>(qnw, knw, positions);
    // 4) per-chunk intra output + KV outer products
    chunk_stats_kernel<<<B_ * NH_ * NC_, 256, SMEM3>>>();
    // 5) prefix scan (overwrites hA region — GEMMs done)
    scan_kernel<<<2048, 256>>>(rec);
    // 6) inter-chunk output
    o_inter_kernel<<<B_ * NH_ * NC_, 256, SMEM6>>>();
    // 7) grouped RMSNorm + gate (+ tf32 rounding of dense GEMM A operand)
    gating_kernel<<<B_ * S_, 256>>>(gnw);
    // 8) dense projection -> d_out
    gemm_pipe<<<dim3(8, 32), 256, GSM>>>(op, wD, out, 4096, NHD, 2048);
}